// round 13
// baseline (speedup 1.0000x reference)
#include <cuda_runtime.h>
#include <cuda_bf16.h>
#include <cstdint>

// ---------------------------------------------------------------------------
// MemristiveLinear == y = x @ w + b (512^3 fp32), tcgen05 bf16 split:
//   x = xh+xl, w = wh+wl;  y ~= xh@wh + xh@wl + xl@wh  (+b)
//
// R13: R12 with the serial convert chain halved and overlapped with MMA:
//   - 1024 threads (convert work per thread halves)
//   - two-phase pipeline: convert k<128 -> sync -> dispatch ks 0..7 ->
//     convert k>=128 (overlaps MMA) -> sync -> dispatch ks 8..15 -> commit
//   - epilogue via 2x LDTM x16 (caps regs at 1024 threads); winner reads
//     both partials (p0+p1+bias, fixed order, deterministic)
// Join (atomic semaphore + tid0 gpu fences) and all tcgen05 constants are
// the R10-R12 validated ones. Generic compute_103 pass gets a correct
// fallback body (never runs; sm_103a cubin preferred).
// ---------------------------------------------------------------------------

#if defined(__CUDA_ARCH_FEAT_SM103_ALL) || defined(__CUDA_ARCH_FEAT_SM100_ALL) || \
    defined(__CUDA_ARCH_FEAT_SM101_ALL) || defined(__CUDA_ARCH_SPECIFIC__) ||     \
    defined(__CUDA_ARCH_FAMILY_SPECIFIC__)
#define TC_OK 1
#else
#define TC_OK 0
#endif

#define MD 512
#define ND 512
#define KD 512
#define KH 256                       // K per split-K half
#define NT 1024

__device__ float gPart[2][MD * ND];  // split-K partials (2 MB)
__device__ int gCnt[64];             // per-tile semaphores (zero-init)

#define SWZ(o) ((o) ^ (((o) >> 3) & 0x70))
#define DESC_BASE 0x4000404000010000ull
#define MK_DESC(addr) (DESC_BASE | (((unsigned long long)((addr) >> 4)) & 0x3FFF))
// kind::f16 idesc: F32 acc, BF16 a/b, M=128, N=32 (validated R5-R12)
#define IDESC ((1u << 4) | (1u << 7) | (1u << 10) | (4u << 17) | (8u << 24))

// smem map (relative to 1024-aligned base):
//   0: tmem ptr | 8: mbar | 64: win flag | 128: bias[32]
//   Ah @ 1024 (64K) | Al @ 66560 (64K) | Wh @ 132096 (16K) | Wl @ 148480 (16K)
#define OFF_AH 1024
#define OFF_AL 66560
#define OFF_WH 132096
#define OFF_WL 148480
#define SMEM_DYN 166912

__device__ __forceinline__ uint32_t s2u(const void* p) {
    uint32_t a;
    asm("{ .reg .u64 t; cvta.to.shared.u64 t, %1; cvt.u32.u64 %0, t; }"
        : "=r"(a) : "l"(p));
    return a;
}

// Split two fp32 into packed bf16x2 hi + lo (a in low half). Validated R6-R12.
__device__ __forceinline__ void split2(float a, float b, unsigned& h,
                                       unsigned& l) {
    unsigned hp;
    asm("cvt.rn.bf16x2.f32 %0, %1, %2;" : "=r"(hp) : "f"(b), "f"(a));
    float fa = __uint_as_float(hp << 16);
    float fb = __uint_as_float(hp & 0xffff0000u);
    float ra = a - fa;
    float rb = b - fb;
    asm("cvt.rn.bf16x2.f32 %0, %1, %2;" : "=r"(l) : "f"(rb), "f"(ra));
    h = hp;
}

#if TC_OK
__device__ __forceinline__ void mma_f16_ss(uint32_t d, unsigned long long ad,
                                           unsigned long long bd,
                                           uint32_t idesc, uint32_t en) {
    asm volatile(
        "{\n\t.reg .pred p;\n\tsetp.ne.u32 p, %5, 0;\n\t"
        "tcgen05.mma.cta_group::1.kind::f16 [%0], %1, %2, %3, {%4, %4, %4, %4}, p;\n\t}"
        :: "r"(d), "l"(ad), "l"(bd), "r"(idesc), "r"(0u), "r"(en)
        : "memory");
}

#define MBAR_INIT(a) \
    asm volatile("mbarrier.init.shared.b64 [%0], %1;" :: "r"(a), "r"(1u) : "memory")

#define MBAR_WAITP(a, ph) do {                                                \
    unsigned _m = (a), _p = (ph), _d;                                         \
    asm volatile("{\n\t.reg .pred p;\n\t"                                     \
        "mbarrier.try_wait.parity.acquire.cta.shared::cta.b64 p, [%1], %2;\n\t" \
        "selp.b32 %0, 1, 0, p;\n\t}" : "=r"(_d) : "r"(_m), "r"(_p) : "memory"); \
    if (!_d) {                                                                \
        asm volatile("{\n\t.reg .pred P1;\n\t"                                \
            "WL_%=:\n\t"                                                      \
            "mbarrier.try_wait.parity.acquire.cta.shared::cta.b64 P1, [%0], %1, 0x989680;\n\t" \
            "@P1 bra.uni WD_%=;\n\t"                                          \
            "bra.uni WL_%=;\n\t"                                              \
            "WD_%=:\n\t}" :: "r"(_m), "r"(_p) : "memory");                    \
    }                                                                         \
} while (0)

#define TC_COMMIT(a) \
    asm volatile("tcgen05.commit.cta_group::1.mbarrier::arrive::one.shared::cluster.b64 [%0];" \
                 :: "r"(a) : "memory")

#define LDTM_X16(r, addr)                                                     \
    asm volatile("tcgen05.ld.sync.aligned.32x32b.x16.b32 "                    \
        "{%0, %1, %2, %3, %4, %5, %6, %7, "                                   \
        " %8, %9, %10, %11, %12, %13, %14, %15}, [%16];"                      \
        : "=r"((r)[0]),  "=r"((r)[1]),  "=r"((r)[2]),  "=r"((r)[3]),          \
          "=r"((r)[4]),  "=r"((r)[5]),  "=r"((r)[6]),  "=r"((r)[7]),          \
          "=r"((r)[8]),  "=r"((r)[9]),  "=r"((r)[10]), "=r"((r)[11]),         \
          "=r"((r)[12]), "=r"((r)[13]), "=r"((r)[14]), "=r"((r)[15])          \
        : "r"(addr))
#endif  // TC_OK

#if TC_OK
// Convert one phase (ph = 0/1 -> k in [128ph, 128ph+128)) of A and W.
__device__ __forceinline__ void convert_phase(
    const float* __restrict__ X, const float* __restrict__ W, char* dbase,
    int tid, int m0, int n0, int kz, int ph) {
    // ---- A: 128 m x 128 k fp32, 4096 float4, 4 per thread ----------------
    {
        const int arow0 = tid >> 5;          // + 32*j
        const int kq = tid & 31;             // float4 idx within 128-k half
        const int ac = 2 * ph + (kq >> 4);   // atom col
        const int aicb = ((4 * kq) & 63) * 2;
        const float* xb = X + kz * KH + ph * 128 + 4 * kq;
#pragma unroll
        for (int j = 0; j < 4; j++) {
            const int row = j * 32 + arow0;
            float4 v = *(const float4*)(xb + (size_t)(m0 + row) * KD);
            unsigned h01, l01, h23, l23;
            split2(v.x, v.y, h01, l01);
            split2(v.z, v.w, h23, l23);
            const int off = SWZ(((row >> 3) + ac * 16) * 1024 +
                                (row & 7) * 128 + aicb);
            *(uint2*)(dbase + OFF_AH + off) = make_uint2(h01, h23);
            *(uint2*)(dbase + OFF_AL + off) = make_uint2(l01, l23);
        }
    }
    // ---- W: 32 n x 128 k (lane = n column, coalesced), 2 pairs/thread ----
    {
        const int wn = tid & 31;
        const float* wb = W + (size_t)(kz * KH) * ND + n0 + wn;
        const int nbase = (wn >> 3) * 1024 + (wn & 7) * 128;
#pragma unroll
        for (int it = 0; it < 2; it++) {
            const int p = (tid >> 5) + 32 * it;       // 0..63
            const int kg = ph * 128 + 2 * p;
            float w0 = wb[(size_t)kg * ND];
            float w1 = wb[(size_t)(kg + 1) * ND];
            unsigned h, l;
            split2(w0, w1, h, l);
            const int off = SWZ(nbase + (kg >> 6) * 4096 + (kg & 63) * 2);
            *(unsigned*)(dbase + OFF_WH + off) = h;
            *(unsigned*)(dbase + OFF_WL + off) = l;
        }
    }
}
#endif

__global__ __launch_bounds__(NT, 1)
void fused_kernel(const float* __restrict__ X, const float* __restrict__ W,
                  const float* __restrict__ Bias, float* __restrict__ Y) {
    extern __shared__ char dsm[];
    const int tid = threadIdx.x;
    const int n0 = blockIdx.x * 32;
    const int m0 = blockIdx.y * 128;
    const int kz = blockIdx.z;            // split-K half 0/1
    const int tile = blockIdx.y * 16 + blockIdx.x;

#if TC_OK
    const uint32_t raw = s2u(dsm);
    const uint32_t base = (raw + 1023u) & ~1023u;
    char* dbase = dsm + (base - raw);

    const int wid = tid >> 5;
    const int lid = tid & 31;

    // Prefetch bias into smem.
    if (tid < 8)
        *(float4*)(dbase + 128 + 16 * tid) = ((const float4*)(Bias + n0))[tid];

    if (wid == 0)
        asm volatile(
            "tcgen05.alloc.cta_group::1.sync.aligned.shared::cta.b32 [%0], %1;"
            :: "r"(base), "r"(64u) : "memory");
    if (tid == 0) MBAR_INIT(base + 8);

    // ---- phase 1: convert k in [0,128) -----------------------------------
    convert_phase(X, W, dbase, tid, m0, n0, kz, 0);
    __syncthreads();                      // BAR drains STS
    uint32_t tmem;
    asm("ld.shared.b32 %0, [%1];" : "=r"(tmem) : "r"(base));

    const unsigned long long ah = MK_DESC(base + OFF_AH);
    const unsigned long long al = MK_DESC(base + OFF_AL);
    const unsigned long long bh = MK_DESC(base + OFF_WH);
    const unsigned long long bl = MK_DESC(base + OFF_WL);

    if (tid == 0) {
        asm volatile("fence.proxy.async.shared::cta;" ::: "memory");
#pragma unroll
        for (int ks = 0; ks < 8; ks++) {
            const int ao = 2 * (ks & 3) + 1024 * (ks >> 2);
            const int bo = 2 * (ks & 3) + 256 * (ks >> 2);
            mma_f16_ss(tmem, ah + ao, bh + bo, IDESC, ks ? 1u : 0u);
            mma_f16_ss(tmem, ah + ao, bl + bo, IDESC, 1u);
            mma_f16_ss(tmem, al + ao, bh + bo, IDESC, 1u);
        }
    }

    // ---- phase 2: convert k in [128,256) (overlaps phase-1 MMAs) ---------
    convert_phase(X, W, dbase, tid, m0, n0, kz, 1);
    __syncthreads();

    if (tid == 0) {
        asm volatile("fence.proxy.async.shared::cta;" ::: "memory");
#pragma unroll
        for (int ks = 8; ks < 16; ks++) {
            const int ao = 2 * (ks & 3) + 1024 * (ks >> 2);
            const int bo = 2 * (ks & 3) + 256 * (ks >> 2);
            mma_f16_ss(tmem, ah + ao, bh + bo, IDESC, 1u);
            mma_f16_ss(tmem, ah + ao, bl + bo, IDESC, 1u);
            mma_f16_ss(tmem, al + ao, bh + bo, IDESC, 1u);
        }
        TC_COMMIT(base + 8);
        MBAR_WAITP(base + 8, 0);          // tid0 alone waits MMA completion
    }
    __syncthreads();
    asm volatile("tcgen05.fence::after_thread_sync;" ::: "memory");

    // ---- publish partial (warps 0-3), 2x LDTM x16 ------------------------
    if (wid < 4) {
        float* pp = &gPart[kz][(size_t)(m0 + wid * 32 + lid) * ND + n0];
#pragma unroll
        for (int h = 0; h < 2; h++) {
            uint32_t d0[16];
            LDTM_X16(d0, tmem + 16 * h);
            asm volatile("tcgen05.wait::ld.sync.aligned;" ::: "memory");
#pragma unroll
            for (int g = 0; g < 4; g++) {
                float4 r;
                r.x = __uint_as_float(d0[4 * g + 0]);
                r.y = __uint_as_float(d0[4 * g + 1]);
                r.z = __uint_as_float(d0[4 * g + 2]);
                r.w = __uint_as_float(d0[4 * g + 3]);
                *(float4*)(pp + 16 * h + 4 * g) = r;
            }
        }
    }

    // ---- fence-promotion join (validated R12) ----------------------------
    __syncthreads();
    if (tid == 0) {
        asm volatile("fence.acq_rel.gpu;" ::: "memory");
        const int old = atomicAdd(&gCnt[tile], 1);
        asm volatile("fence.acq_rel.gpu;" ::: "memory");
        *(int*)(dbase + 64) = (old == 1);
    }
    __syncthreads();

    if (*(int*)(dbase + 64)) {
        // Winner: one float4 of output per thread (1024 x 4 = 4096 = tile).
        const int row = tid >> 3, q = tid & 7;
        const size_t idx = (size_t)(m0 + row) * ND + n0 + 4 * q;
        float4 p0 = *(const float4*)&gPart[0][idx];
        float4 p1 = *(const float4*)&gPart[1][idx];
        float4 bb = *(const float4*)(dbase + 128 + 16 * q);
        float4 r;
        r.x = p0.x + p1.x + bb.x;
        r.y = p0.y + p1.y + bb.y;
        r.z = p0.z + p1.z + bb.z;
        r.w = p0.w + p1.w + bb.w;
        *(float4*)(Y + idx) = r;
        if (tid == 0) gCnt[tile] = 0;     // reset for next graph replay
    }

    __syncthreads();
    if (wid == 0) {
        asm volatile("tcgen05.relinquish_alloc_permit.cta_group::1.sync.aligned;");
        asm volatile("tcgen05.dealloc.cta_group::1.sync.aligned.b32 %0, %1;"
                     :: "r"(tmem), "r"(64u));
    }
#else
    // ---- generic-target fallback (compiles everywhere; never runs) -------
    __shared__ int sflag;
    const int r = tid >> 3;               // 0..127
    const int g = tid & 7;                // 4 n cols each
    float acc[4];
#pragma unroll
    for (int j = 0; j < 4; j++) acc[j] = 0.f;
    for (int k = kz * KH; k < kz * KH + KH; k++) {
        const float a = X[(size_t)(m0 + r) * KD + k];
        const float* wr = W + (size_t)k * ND + n0 + 4 * g;
#pragma unroll
        for (int j = 0; j < 4; j++) acc[j] += a * wr[j];
    }
    {
        float* pp = &gPart[kz][(size_t)(m0 + r) * ND + n0 + 4 * g];
#pragma unroll
        for (int j = 0; j < 4; j++) pp[j] = acc[j];
    }
    __threadfence();
    __syncthreads();
    if (tid == 0) sflag = (atomicAdd(&gCnt[tile], 1) == 1);
    __syncthreads();
    if (sflag) {
        __threadfence();
        const size_t idx = (size_t)(m0 + r) * ND + n0 + 4 * g;
        float4 p0 = *(const float4*)&gPart[0][idx];
        float4 p1 = *(const float4*)&gPart[1][idx];
        const float* bb = Bias + n0 + 4 * g;
        float4 rr;
        rr.x = p0.x + p1.x + bb[0];
        rr.y = p0.y + p1.y + bb[1];
        rr.z = p0.z + p1.z + bb[2];
        rr.w = p0.w + p1.w + bb[3];
        *(float4*)(Y + idx) = rr;
        if (tid == 0) gCnt[tile] = 0;
    }
#endif
}

extern "C" void kernel_launch(void* const* d_in, const int* in_sizes, int n_in,
                              void* d_out, int out_size) {
    const float* x = (const float*)d_in[0];  // [512, 512]
    const float* w = (const float*)d_in[1];  // [512, 512]
    const float* b = (const float*)d_in[2];  // [512]
    float* y = (float*)d_out;                // [512, 512]

    static bool attr_done = false;
    if (!attr_done) {
        cudaFuncSetAttribute(fused_kernel,
                             cudaFuncAttributeMaxDynamicSharedMemorySize,
                             SMEM_DYN);
        attr_done = true;
    }

    dim3 grid(ND / 32, MD / 128, 2);  // (16, 4, 2) = 128 CTAs, one wave
    fused_kernel<<<grid, NT, SMEM_DYN>>>(x, w, b, y);
}

// round 14
// speedup vs baseline: 1.2041x; 1.2041x over previous
#include <cuda_runtime.h>
#include <cuda_bf16.h>
#include <cstdint>

// ---------------------------------------------------------------------------
// MemristiveLinear == y = x @ w + b (512^3 fp32), tcgen05 bf16 split:
//   x = xh+xl, w = wh+wl;  y ~= xh@wh + xh@wl + xl@wh  (+b)
//
// R14: R13 (single launch, split-K x2, 1024 thr, two-phase convert/MMA
//   overlap, fence-promotion join) with three cycle shavings:
//   - phase-2 loads register-prefetched BEFORE the phase-1 sync (the sync
//     blocks hoisting; manual prefetch removes phase-2's exposed LDG latency)
//   - TMEM relinquish/dealloc on warp 1 IN PARALLEL with tid0's join atomic;
//     trailing sync dropped
//   - TMEM alloc 32 cols (all we use)
// All tcgen05 constants and the smem layout are the R5-R13 validated ones.
// Generic compute_103 pass gets a correct fallback body (never runs).
// ---------------------------------------------------------------------------

#if defined(__CUDA_ARCH_FEAT_SM103_ALL) || defined(__CUDA_ARCH_FEAT_SM100_ALL) || \
    defined(__CUDA_ARCH_FEAT_SM101_ALL) || defined(__CUDA_ARCH_SPECIFIC__) ||     \
    defined(__CUDA_ARCH_FAMILY_SPECIFIC__)
#define TC_OK 1
#else
#define TC_OK 0
#endif

#define MD 512
#define ND 512
#define KD 512
#define KH 256                       // K per split-K half
#define NT 1024

__device__ float gPart[2][MD * ND];  // split-K partials (2 MB)
__device__ int gCnt[64];             // per-tile semaphores (zero-init)

#define SWZ(o) ((o) ^ (((o) >> 3) & 0x70))
#define DESC_BASE 0x4000404000010000ull
#define MK_DESC(addr) (DESC_BASE | (((unsigned long long)((addr) >> 4)) & 0x3FFF))
// kind::f16 idesc: F32 acc, BF16 a/b, M=128, N=32 (validated R5-R13)
#define IDESC ((1u << 4) | (1u << 7) | (1u << 10) | (4u << 17) | (8u << 24))

// smem map (relative to 1024-aligned base):
//   0: tmem ptr | 8: mbar | 64: win flag | 128: bias[32]
//   Ah @ 1024 (64K) | Al @ 66560 (64K) | Wh @ 132096 (16K) | Wl @ 148480 (16K)
#define OFF_AH 1024
#define OFF_AL 66560
#define OFF_WH 132096
#define OFF_WL 148480
#define SMEM_DYN 166912

__device__ __forceinline__ uint32_t s2u(const void* p) {
    uint32_t a;
    asm("{ .reg .u64 t; cvta.to.shared.u64 t, %1; cvt.u32.u64 %0, t; }"
        : "=r"(a) : "l"(p));
    return a;
}

// Split two fp32 into packed bf16x2 hi + lo (a in low half). Validated R6-R13.
__device__ __forceinline__ void split2(float a, float b, unsigned& h,
                                       unsigned& l) {
    unsigned hp;
    asm("cvt.rn.bf16x2.f32 %0, %1, %2;" : "=r"(hp) : "f"(b), "f"(a));
    float fa = __uint_as_float(hp << 16);
    float fb = __uint_as_float(hp & 0xffff0000u);
    float ra = a - fa;
    float rb = b - fb;
    asm("cvt.rn.bf16x2.f32 %0, %1, %2;" : "=r"(l) : "f"(rb), "f"(ra));
    h = hp;
}

#if TC_OK
__device__ __forceinline__ void mma_f16_ss(uint32_t d, unsigned long long ad,
                                           unsigned long long bd,
                                           uint32_t idesc, uint32_t en) {
    asm volatile(
        "{\n\t.reg .pred p;\n\tsetp.ne.u32 p, %5, 0;\n\t"
        "tcgen05.mma.cta_group::1.kind::f16 [%0], %1, %2, %3, {%4, %4, %4, %4}, p;\n\t}"
        :: "r"(d), "l"(ad), "l"(bd), "r"(idesc), "r"(0u), "r"(en)
        : "memory");
}

#define MBAR_INIT(a) \
    asm volatile("mbarrier.init.shared.b64 [%0], %1;" :: "r"(a), "r"(1u) : "memory")

#define MBAR_WAITP(a, ph) do {                                                \
    unsigned _m = (a), _p = (ph), _d;                                         \
    asm volatile("{\n\t.reg .pred p;\n\t"                                     \
        "mbarrier.try_wait.parity.acquire.cta.shared::cta.b64 p, [%1], %2;\n\t" \
        "selp.b32 %0, 1, 0, p;\n\t}" : "=r"(_d) : "r"(_m), "r"(_p) : "memory"); \
    if (!_d) {                                                                \
        asm volatile("{\n\t.reg .pred P1;\n\t"                                \
            "WL_%=:\n\t"                                                      \
            "mbarrier.try_wait.parity.acquire.cta.shared::cta.b64 P1, [%0], %1, 0x989680;\n\t" \
            "@P1 bra.uni WD_%=;\n\t"                                          \
            "bra.uni WL_%=;\n\t"                                              \
            "WD_%=:\n\t}" :: "r"(_m), "r"(_p) : "memory");                    \
    }                                                                         \
} while (0)

#define TC_COMMIT(a) \
    asm volatile("tcgen05.commit.cta_group::1.mbarrier::arrive::one.shared::cluster.b64 [%0];" \
                 :: "r"(a) : "memory")

#define LDTM_X16(r, addr)                                                     \
    asm volatile("tcgen05.ld.sync.aligned.32x32b.x16.b32 "                    \
        "{%0, %1, %2, %3, %4, %5, %6, %7, "                                   \
        " %8, %9, %10, %11, %12, %13, %14, %15}, [%16];"                      \
        : "=r"((r)[0]),  "=r"((r)[1]),  "=r"((r)[2]),  "=r"((r)[3]),          \
          "=r"((r)[4]),  "=r"((r)[5]),  "=r"((r)[6]),  "=r"((r)[7]),          \
          "=r"((r)[8]),  "=r"((r)[9]),  "=r"((r)[10]), "=r"((r)[11]),         \
          "=r"((r)[12]), "=r"((r)[13]), "=r"((r)[14]), "=r"((r)[15])          \
        : "r"(addr))
#endif  // TC_OK

__global__ __launch_bounds__(NT, 1)
void fused_kernel(const float* __restrict__ X, const float* __restrict__ W,
                  const float* __restrict__ Bias, float* __restrict__ Y) {
    extern __shared__ char dsm[];
    const int tid = threadIdx.x;
    const int n0 = blockIdx.x * 32;
    const int m0 = blockIdx.y * 128;
    const int kz = blockIdx.z;            // split-K half 0/1
    const int tile = blockIdx.y * 16 + blockIdx.x;

#if TC_OK
    const uint32_t raw = s2u(dsm);
    const uint32_t base = (raw + 1023u) & ~1023u;
    char* dbase = dsm + (base - raw);

    const int wid = tid >> 5;
    const int lid = tid & 31;

    // Prefetch bias into smem.
    if (tid < 8)
        *(float4*)(dbase + 128 + 16 * tid) = ((const float4*)(Bias + n0))[tid];

    if (wid == 0)
        asm volatile(
            "tcgen05.alloc.cta_group::1.sync.aligned.shared::cta.b32 [%0], %1;"
            :: "r"(base), "r"(32u) : "memory");
    if (tid == 0) MBAR_INIT(base + 8);

    // ---- convert geometry (validated R13) --------------------------------
    const int arow0 = tid >> 5;            // + 32*j
    const int kq = tid & 31;               // float4 idx within 128-k half
    const int aicb = ((4 * kq) & 63) * 2;  // byte off within atom row
    const float* xb = X + kz * KH + 4 * kq;
    const int wn = tid & 31;               // lane = n column (coalesced)
    const int wp = tid >> 5;               // k-pair selector (0..31)
    const float* wb = W + (size_t)(kz * KH) * ND + n0 + wn;
    const int nbase = (wn >> 3) * 1024 + (wn & 7) * 128;

    // ---- phase 1: load + convert k in [0,128) ----------------------------
    {
        float4 xr[4];
#pragma unroll
        for (int j = 0; j < 4; j++)
            xr[j] = *(const float4*)(xb + (size_t)(m0 + j * 32 + arow0) * KD);
        float w0a = wb[(size_t)(2 * wp) * ND];
        float w1a = wb[(size_t)(2 * wp + 1) * ND];
        float w0b = wb[(size_t)(64 + 2 * wp) * ND];
        float w1b = wb[(size_t)(64 + 2 * wp + 1) * ND];

#pragma unroll
        for (int j = 0; j < 4; j++) {
            const int row = j * 32 + arow0;
            unsigned h01, l01, h23, l23;
            split2(xr[j].x, xr[j].y, h01, l01);
            split2(xr[j].z, xr[j].w, h23, l23);
            const int ac = kq >> 4;        // ph=0 atom col
            const int off = SWZ(((row >> 3) + ac * 16) * 1024 +
                                (row & 7) * 128 + aicb);
            *(uint2*)(dbase + OFF_AH + off) = make_uint2(h01, h23);
            *(uint2*)(dbase + OFF_AL + off) = make_uint2(l01, l23);
        }
        {
            unsigned h, l;
            const int kg = 2 * wp;
            split2(w0a, w1a, h, l);
            const int off = SWZ(nbase + (kg >> 6) * 4096 + (kg & 63) * 2);
            *(unsigned*)(dbase + OFF_WH + off) = h;
            *(unsigned*)(dbase + OFF_WL + off) = l;
        }
        {
            unsigned h, l;
            const int kg = 64 + 2 * wp;
            split2(w0b, w1b, h, l);
            const int off = SWZ(nbase + (kg >> 6) * 4096 + (kg & 63) * 2);
            *(unsigned*)(dbase + OFF_WH + off) = h;
            *(unsigned*)(dbase + OFF_WL + off) = l;
        }
    }

    // ---- phase-2 register prefetch (BEFORE the sync, so LDG latency
    //      overlaps the barrier + phase-1 MMA dispatches) ------------------
    float4 xr2[2];
#pragma unroll
    for (int j = 0; j < 2; j++)
        xr2[j] =
            *(const float4*)(xb + 128 + (size_t)(m0 + j * 32 + arow0) * KD);
    float pw0a = wb[(size_t)(128 + 2 * wp) * ND];
    float pw1a = wb[(size_t)(128 + 2 * wp + 1) * ND];
    float pw0b = wb[(size_t)(192 + 2 * wp) * ND];
    float pw1b = wb[(size_t)(192 + 2 * wp + 1) * ND];

    __syncthreads();                      // BAR drains phase-1 STS
    uint32_t tmem;
    asm("ld.shared.b32 %0, [%1];" : "=r"(tmem) : "r"(base));

    const unsigned long long ah = MK_DESC(base + OFF_AH);
    const unsigned long long al = MK_DESC(base + OFF_AL);
    const unsigned long long bh = MK_DESC(base + OFF_WH);
    const unsigned long long bl = MK_DESC(base + OFF_WL);

    if (tid == 0) {
        asm volatile("fence.proxy.async.shared::cta;" ::: "memory");
#pragma unroll
        for (int ks = 0; ks < 8; ks++) {
            const int ao = 2 * (ks & 3) + 1024 * (ks >> 2);
            const int bo = 2 * (ks & 3) + 256 * (ks >> 2);
            mma_f16_ss(tmem, ah + ao, bh + bo, IDESC, ks ? 1u : 0u);
            mma_f16_ss(tmem, ah + ao, bl + bo, IDESC, 1u);
            mma_f16_ss(tmem, al + ao, bh + bo, IDESC, 1u);
        }
    }

    // ---- phase 2: convert k in [128,256) (A rows 2,3 loaded now; rows 0,1
    //      and all W pairs were prefetched) --------------------------------
    {
        float4 xr3[2];
#pragma unroll
        for (int j = 2; j < 4; j++)
            xr3[j - 2] =
                *(const float4*)(xb + 128 + (size_t)(m0 + j * 32 + arow0) * KD);

#pragma unroll
        for (int j = 0; j < 4; j++) {
            const float4 v = (j < 2) ? xr2[j] : xr3[j - 2];
            const int row = j * 32 + arow0;
            unsigned h01, l01, h23, l23;
            split2(v.x, v.y, h01, l01);
            split2(v.z, v.w, h23, l23);
            const int ac = 2 + (kq >> 4);  // ph=1 atom col
            const int off = SWZ(((row >> 3) + ac * 16) * 1024 +
                                (row & 7) * 128 + aicb);
            *(uint2*)(dbase + OFF_AH + off) = make_uint2(h01, h23);
            *(uint2*)(dbase + OFF_AL + off) = make_uint2(l01, l23);
        }
        {
            unsigned h, l;
            const int kg = 128 + 2 * wp;
            split2(pw0a, pw1a, h, l);
            const int off = SWZ(nbase + (kg >> 6) * 4096 + (kg & 63) * 2);
            *(unsigned*)(dbase + OFF_WH + off) = h;
            *(unsigned*)(dbase + OFF_WL + off) = l;
        }
        {
            unsigned h, l;
            const int kg = 192 + 2 * wp;
            split2(pw0b, pw1b, h, l);
            const int off = SWZ(nbase + (kg >> 6) * 4096 + (kg & 63) * 2);
            *(unsigned*)(dbase + OFF_WH + off) = h;
            *(unsigned*)(dbase + OFF_WL + off) = l;
        }
    }
    __syncthreads();

    if (tid == 0) {
        asm volatile("fence.proxy.async.shared::cta;" ::: "memory");
#pragma unroll
        for (int ks = 8; ks < 16; ks++) {
            const int ao = 2 * (ks & 3) + 1024 * (ks >> 2);
            const int bo = 2 * (ks & 3) + 256 * (ks >> 2);
            mma_f16_ss(tmem, ah + ao, bh + bo, IDESC, 1u);
            mma_f16_ss(tmem, ah + ao, bl + bo, IDESC, 1u);
            mma_f16_ss(tmem, al + ao, bh + bo, IDESC, 1u);
        }
        TC_COMMIT(base + 8);
        MBAR_WAITP(base + 8, 0);          // tid0 alone waits MMA completion
    }
    __syncthreads();
    asm volatile("tcgen05.fence::after_thread_sync;" ::: "memory");

    // ---- publish partial (warps 0-3), 2x LDTM x16 ------------------------
    if (wid < 4) {
        float* pp = &gPart[kz][(size_t)(m0 + wid * 32 + lid) * ND + n0];
#pragma unroll
        for (int h = 0; h < 2; h++) {
            uint32_t d0[16];
            LDTM_X16(d0, tmem + 16 * h);
            asm volatile("tcgen05.wait::ld.sync.aligned;" ::: "memory");
#pragma unroll
            for (int g = 0; g < 4; g++) {
                float4 r;
                r.x = __uint_as_float(d0[4 * g + 0]);
                r.y = __uint_as_float(d0[4 * g + 1]);
                r.z = __uint_as_float(d0[4 * g + 2]);
                r.w = __uint_as_float(d0[4 * g + 3]);
                *(float4*)(pp + 16 * h + 4 * g) = r;
            }
        }
    }

    // ---- join: warp1 deallocs TMEM in PARALLEL with tid0's atomic --------
    __syncthreads();                      // STGs + all TMEM reads complete
    if (wid == 1) {
        asm volatile("tcgen05.relinquish_alloc_permit.cta_group::1.sync.aligned;");
        asm volatile("tcgen05.dealloc.cta_group::1.sync.aligned.b32 %0, %1;"
                     :: "r"(tmem), "r"(32u));
    }
    if (tid == 0) {
        asm volatile("fence.acq_rel.gpu;" ::: "memory");
        const int old = atomicAdd(&gCnt[tile], 1);
        asm volatile("fence.acq_rel.gpu;" ::: "memory");
        *(int*)(dbase + 64) = (old == 1);
    }
    __syncthreads();

    if (*(int*)(dbase + 64)) {
        // Winner: one float4 of output per thread (1024 x 4 = 4096 = tile).
        const int row = tid >> 3, q = tid & 7;
        const size_t idx = (size_t)(m0 + row) * ND + n0 + 4 * q;
        float4 p0 = *(const float4*)&gPart[0][idx];
        float4 p1 = *(const float4*)&gPart[1][idx];
        float4 bb = *(const float4*)(dbase + 128 + 16 * q);
        float4 r;
        r.x = p0.x + p1.x + bb.x;
        r.y = p0.y + p1.y + bb.y;
        r.z = p0.z + p1.z + bb.z;
        r.w = p0.w + p1.w + bb.w;
        *(float4*)(Y + idx) = r;
        if (tid == 0) gCnt[tile] = 0;     // reset for next graph replay
    }
    // no trailing sync: each warp exits when its own tail is done
#else
    // ---- generic-target fallback (compiles everywhere; never runs) -------
    __shared__ int sflag;
    const int r = tid >> 3;               // 0..127
    const int g = tid & 7;                // 4 n cols each
    float acc[4];
#pragma unroll
    for (int j = 0; j < 4; j++) acc[j] = 0.f;
    for (int k = kz * KH; k < kz * KH + KH; k++) {
        const float a = X[(size_t)(m0 + r) * KD + k];
        const float* wr = W + (size_t)k * ND + n0 + 4 * g;
#pragma unroll
        for (int j = 0; j < 4; j++) acc[j] += a * wr[j];
    }
    {
        float* pp = &gPart[kz][(size_t)(m0 + r) * ND + n0 + 4 * g];
#pragma unroll
        for (int j = 0; j < 4; j++) pp[j] = acc[j];
    }
    __threadfence();
    __syncthreads();
    if (tid == 0) sflag = (atomicAdd(&gCnt[tile], 1) == 1);
    __syncthreads();
    if (sflag) {
        __threadfence();
        const size_t idx = (size_t)(m0 + r) * ND + n0 + 4 * g;
        float4 p0 = *(const float4*)&gPart[0][idx];
        float4 p1 = *(const float4*)&gPart[1][idx];
        const float* bb = Bias + n0 + 4 * g;
        float4 rr;
        rr.x = p0.x + p1.x + bb[0];
        rr.y = p0.y + p1.y + bb[1];
        rr.z = p0.z + p1.z + bb[2];
        rr.w = p0.w + p1.w + bb[3];
        *(float4*)(Y + idx) = rr;
        if (tid == 0) gCnt[tile] = 0;
    }
#endif
}

extern "C" void kernel_launch(void* const* d_in, const int* in_sizes, int n_in,
                              void* d_out, int out_size) {
    const float* x = (const float*)d_in[0];  // [512, 512]
    const float* w = (const float*)d_in[1];  // [512, 512]
    const float* b = (const float*)d_in[2];  // [512]
    float* y = (float*)d_out;                // [512, 512]

    static bool attr_done = false;
    if (!attr_done) {
        cudaFuncSetAttribute(fused_kernel,
                             cudaFuncAttributeMaxDynamicSharedMemorySize,
                             SMEM_DYN);
        attr_done = true;
    }

    dim3 grid(ND / 32, MD / 128, 2);  // (16, 4, 2) = 128 CTAs, one wave
    fused_kernel<<<grid, NT, SMEM_DYN>>>(x, w, b, y);
}

// round 15
// speedup vs baseline: 1.2149x; 1.0090x over previous
#include <cuda_runtime.h>
#include <cuda_bf16.h>
#include <cstdint>

// ---------------------------------------------------------------------------
// MemristiveLinear == y = x @ w + b (512^3 fp32), tcgen05 bf16 split:
//   x = xh+xl, w = wh+wl;  y ~= xh@wh + xh@wl + xl@wh  (+b)
//
// R15: R14 (single launch, split-K x2, 1024 thr, two-phase convert/MMA
//   overlap, cross-sync register prefetch, parallel dealloc, fence-promotion
//   join) with three head/tail reorderings:
//   - phase-1 LDGs issued BEFORE bias/TMEM-alloc/mbar-init (DRAM latency
//     overlaps the alloc chain; the alloc's memory clobber otherwise blocks
//     hoisting)
//   - warps 0-3 wait the commit mbarrier DIRECTLY (test_mma.cu pattern),
//     removing the tid0-wait -> syncthreads serialization
//   - both LDTM x16 issued before a single wait::ld
// All tcgen05 constants and the smem layout are the R5-R14 validated ones.
// Generic compute_103 pass gets a correct fallback body (never runs).
// ---------------------------------------------------------------------------

#if defined(__CUDA_ARCH_FEAT_SM103_ALL) || defined(__CUDA_ARCH_FEAT_SM100_ALL) || \
    defined(__CUDA_ARCH_FEAT_SM101_ALL) || defined(__CUDA_ARCH_SPECIFIC__) ||     \
    defined(__CUDA_ARCH_FAMILY_SPECIFIC__)
#define TC_OK 1
#else
#define TC_OK 0
#endif

#define MD 512
#define ND 512
#define KD 512
#define KH 256                       // K per split-K half
#define NT 1024

__device__ float gPart[2][MD * ND];  // split-K partials (2 MB)
__device__ int gCnt[64];             // per-tile semaphores (zero-init)

#define SWZ(o) ((o) ^ (((o) >> 3) & 0x70))
#define DESC_BASE 0x4000404000010000ull
#define MK_DESC(addr) (DESC_BASE | (((unsigned long long)((addr) >> 4)) & 0x3FFF))
// kind::f16 idesc: F32 acc, BF16 a/b, M=128, N=32 (validated R5-R14)
#define IDESC ((1u << 4) | (1u << 7) | (1u << 10) | (4u << 17) | (8u << 24))

// smem map (relative to 1024-aligned base):
//   0: tmem ptr | 8: mbar | 64: win flag | 128: bias[32]
//   Ah @ 1024 (64K) | Al @ 66560 (64K) | Wh @ 132096 (16K) | Wl @ 148480 (16K)
#define OFF_AH 1024
#define OFF_AL 66560
#define OFF_WH 132096
#define OFF_WL 148480
#define SMEM_DYN 166912

__device__ __forceinline__ uint32_t s2u(const void* p) {
    uint32_t a;
    asm("{ .reg .u64 t; cvta.to.shared.u64 t, %1; cvt.u32.u64 %0, t; }"
        : "=r"(a) : "l"(p));
    return a;
}

// Split two fp32 into packed bf16x2 hi + lo (a in low half). Validated R6-R14.
__device__ __forceinline__ void split2(float a, float b, unsigned& h,
                                       unsigned& l) {
    unsigned hp;
    asm("cvt.rn.bf16x2.f32 %0, %1, %2;" : "=r"(hp) : "f"(b), "f"(a));
    float fa = __uint_as_float(hp << 16);
    float fb = __uint_as_float(hp & 0xffff0000u);
    float ra = a - fa;
    float rb = b - fb;
    asm("cvt.rn.bf16x2.f32 %0, %1, %2;" : "=r"(l) : "f"(rb), "f"(ra));
    h = hp;
}

#if TC_OK
__device__ __forceinline__ void mma_f16_ss(uint32_t d, unsigned long long ad,
                                           unsigned long long bd,
                                           uint32_t idesc, uint32_t en) {
    asm volatile(
        "{\n\t.reg .pred p;\n\tsetp.ne.u32 p, %5, 0;\n\t"
        "tcgen05.mma.cta_group::1.kind::f16 [%0], %1, %2, %3, {%4, %4, %4, %4}, p;\n\t}"
        :: "r"(d), "l"(ad), "l"(bd), "r"(idesc), "r"(0u), "r"(en)
        : "memory");
}

#define MBAR_INIT(a) \
    asm volatile("mbarrier.init.shared.b64 [%0], %1;" :: "r"(a), "r"(1u) : "memory")

#define MBAR_WAITP(a, ph) do {                                                \
    unsigned _m = (a), _p = (ph), _d;                                         \
    asm volatile("{\n\t.reg .pred p;\n\t"                                     \
        "mbarrier.try_wait.parity.acquire.cta.shared::cta.b64 p, [%1], %2;\n\t" \
        "selp.b32 %0, 1, 0, p;\n\t}" : "=r"(_d) : "r"(_m), "r"(_p) : "memory"); \
    if (!_d) {                                                                \
        asm volatile("{\n\t.reg .pred P1;\n\t"                                \
            "WL_%=:\n\t"                                                      \
            "mbarrier.try_wait.parity.acquire.cta.shared::cta.b64 P1, [%0], %1, 0x989680;\n\t" \
            "@P1 bra.uni WD_%=;\n\t"                                          \
            "bra.uni WL_%=;\n\t"                                              \
            "WD_%=:\n\t}" :: "r"(_m), "r"(_p) : "memory");                    \
    }                                                                         \
} while (0)

#define TC_COMMIT(a) \
    asm volatile("tcgen05.commit.cta_group::1.mbarrier::arrive::one.shared::cluster.b64 [%0];" \
                 :: "r"(a) : "memory")

#define LDTM_X16(r, addr)                                                     \
    asm volatile("tcgen05.ld.sync.aligned.32x32b.x16.b32 "                    \
        "{%0, %1, %2, %3, %4, %5, %6, %7, "                                   \
        " %8, %9, %10, %11, %12, %13, %14, %15}, [%16];"                      \
        : "=r"((r)[0]),  "=r"((r)[1]),  "=r"((r)[2]),  "=r"((r)[3]),          \
          "=r"((r)[4]),  "=r"((r)[5]),  "=r"((r)[6]),  "=r"((r)[7]),          \
          "=r"((r)[8]),  "=r"((r)[9]),  "=r"((r)[10]), "=r"((r)[11]),         \
          "=r"((r)[12]), "=r"((r)[13]), "=r"((r)[14]), "=r"((r)[15])          \
        : "r"(addr))
#endif  // TC_OK

__global__ __launch_bounds__(NT, 1)
void fused_kernel(const float* __restrict__ X, const float* __restrict__ W,
                  const float* __restrict__ Bias, float* __restrict__ Y) {
    extern __shared__ char dsm[];
    const int tid = threadIdx.x;
    const int n0 = blockIdx.x * 32;
    const int m0 = blockIdx.y * 128;
    const int kz = blockIdx.z;            // split-K half 0/1
    const int tile = blockIdx.y * 16 + blockIdx.x;

#if TC_OK
    const uint32_t raw = s2u(dsm);
    const uint32_t base = (raw + 1023u) & ~1023u;
    char* dbase = dsm + (base - raw);

    const int wid = tid >> 5;
    const int lid = tid & 31;

    // ---- convert geometry (validated R13/R14) ----------------------------
    const int arow0 = tid >> 5;            // + 32*j
    const int kq = tid & 31;               // float4 idx within 128-k half
    const int aicb = ((4 * kq) & 63) * 2;  // byte off within atom row
    const float* xb = X + kz * KH + 4 * kq;
    const int wn = tid & 31;               // lane = n column (coalesced)
    const int wp = tid >> 5;               // k-pair selector (0..31)
    const float* wb = W + (size_t)(kz * KH) * ND + n0 + wn;
    const int nbase = (wn >> 3) * 1024 + (wn & 7) * 128;

    // ---- issue ALL phase-1 LDGs first: their DRAM latency overlaps the
    //      bias prefetch, TMEM alloc and mbar init below -------------------
    float4 xr[4];
#pragma unroll
    for (int j = 0; j < 4; j++)
        xr[j] = *(const float4*)(xb + (size_t)(m0 + j * 32 + arow0) * KD);
    float w0a = wb[(size_t)(2 * wp) * ND];
    float w1a = wb[(size_t)(2 * wp + 1) * ND];
    float w0b = wb[(size_t)(64 + 2 * wp) * ND];
    float w1b = wb[(size_t)(64 + 2 * wp + 1) * ND];

    // Prefetch bias into smem.
    if (tid < 8)
        *(float4*)(dbase + 128 + 16 * tid) = ((const float4*)(Bias + n0))[tid];

    if (wid == 0)
        asm volatile(
            "tcgen05.alloc.cta_group::1.sync.aligned.shared::cta.b32 [%0], %1;"
            :: "r"(base), "r"(32u) : "memory");
    if (tid == 0) MBAR_INIT(base + 8);

    // ---- phase 1: convert k in [0,128) (data already in flight) ----------
    {
#pragma unroll
        for (int j = 0; j < 4; j++) {
            const int row = j * 32 + arow0;
            unsigned h01, l01, h23, l23;
            split2(xr[j].x, xr[j].y, h01, l01);
            split2(xr[j].z, xr[j].w, h23, l23);
            const int ac = kq >> 4;        // ph=0 atom col
            const int off = SWZ(((row >> 3) + ac * 16) * 1024 +
                                (row & 7) * 128 + aicb);
            *(uint2*)(dbase + OFF_AH + off) = make_uint2(h01, h23);
            *(uint2*)(dbase + OFF_AL + off) = make_uint2(l01, l23);
        }
        {
            unsigned h, l;
            const int kg = 2 * wp;
            split2(w0a, w1a, h, l);
            const int off = SWZ(nbase + (kg >> 6) * 4096 + (kg & 63) * 2);
            *(unsigned*)(dbase + OFF_WH + off) = h;
            *(unsigned*)(dbase + OFF_WL + off) = l;
        }
        {
            unsigned h, l;
            const int kg = 64 + 2 * wp;
            split2(w0b, w1b, h, l);
            const int off = SWZ(nbase + (kg >> 6) * 4096 + (kg & 63) * 2);
            *(unsigned*)(dbase + OFF_WH + off) = h;
            *(unsigned*)(dbase + OFF_WL + off) = l;
        }
    }

    // ---- phase-2 register prefetch (BEFORE the sync; overlaps barrier +
    //      phase-1 MMA dispatches) -----------------------------------------
    float4 xr2[2];
#pragma unroll
    for (int j = 0; j < 2; j++)
        xr2[j] =
            *(const float4*)(xb + 128 + (size_t)(m0 + j * 32 + arow0) * KD);
    float pw0a = wb[(size_t)(128 + 2 * wp) * ND];
    float pw1a = wb[(size_t)(128 + 2 * wp + 1) * ND];
    float pw0b = wb[(size_t)(192 + 2 * wp) * ND];
    float pw1b = wb[(size_t)(192 + 2 * wp + 1) * ND];

    __syncthreads();                      // BAR drains phase-1 STS
    uint32_t tmem;
    asm("ld.shared.b32 %0, [%1];" : "=r"(tmem) : "r"(base));

    const unsigned long long ah = MK_DESC(base + OFF_AH);
    const unsigned long long al = MK_DESC(base + OFF_AL);
    const unsigned long long bh = MK_DESC(base + OFF_WH);
    const unsigned long long bl = MK_DESC(base + OFF_WL);

    if (tid == 0) {
        asm volatile("fence.proxy.async.shared::cta;" ::: "memory");
#pragma unroll
        for (int ks = 0; ks < 8; ks++) {
            const int ao = 2 * (ks & 3) + 1024 * (ks >> 2);
            const int bo = 2 * (ks & 3) + 256 * (ks >> 2);
            mma_f16_ss(tmem, ah + ao, bh + bo, IDESC, ks ? 1u : 0u);
            mma_f16_ss(tmem, ah + ao, bl + bo, IDESC, 1u);
            mma_f16_ss(tmem, al + ao, bh + bo, IDESC, 1u);
        }
    }

    // ---- phase 2: convert k in [128,256) ---------------------------------
    {
        float4 xr3[2];
#pragma unroll
        for (int j = 2; j < 4; j++)
            xr3[j - 2] =
                *(const float4*)(xb + 128 + (size_t)(m0 + j * 32 + arow0) * KD);

#pragma unroll
        for (int j = 0; j < 4; j++) {
            const float4 v = (j < 2) ? xr2[j] : xr3[j - 2];
            const int row = j * 32 + arow0;
            unsigned h01, l01, h23, l23;
            split2(v.x, v.y, h01, l01);
            split2(v.z, v.w, h23, l23);
            const int ac = 2 + (kq >> 4);  // ph=1 atom col
            const int off = SWZ(((row >> 3) + ac * 16) * 1024 +
                                (row & 7) * 128 + aicb);
            *(uint2*)(dbase + OFF_AH + off) = make_uint2(h01, h23);
            *(uint2*)(dbase + OFF_AL + off) = make_uint2(l01, l23);
        }
        {
            unsigned h, l;
            const int kg = 128 + 2 * wp;
            split2(pw0a, pw1a, h, l);
            const int off = SWZ(nbase + (kg >> 6) * 4096 + (kg & 63) * 2);
            *(unsigned*)(dbase + OFF_WH + off) = h;
            *(unsigned*)(dbase + OFF_WL + off) = l;
        }
        {
            unsigned h, l;
            const int kg = 192 + 2 * wp;
            split2(pw0b, pw1b, h, l);
            const int off = SWZ(nbase + (kg >> 6) * 4096 + (kg & 63) * 2);
            *(unsigned*)(dbase + OFF_WH + off) = h;
            *(unsigned*)(dbase + OFF_WL + off) = l;
        }
    }
    __syncthreads();

    if (tid == 0) {
        asm volatile("fence.proxy.async.shared::cta;" ::: "memory");
#pragma unroll
        for (int ks = 8; ks < 16; ks++) {
            const int ao = 2 * (ks & 3) + 1024 * (ks >> 2);
            const int bo = 2 * (ks & 3) + 256 * (ks >> 2);
            mma_f16_ss(tmem, ah + ao, bh + bo, IDESC, 1u);
            mma_f16_ss(tmem, ah + ao, bl + bo, IDESC, 1u);
            mma_f16_ss(tmem, al + ao, bh + bo, IDESC, 1u);
        }
        TC_COMMIT(base + 8);
    }

    // ---- warps 0-3 wait MMA completion DIRECTLY (broadcast parity wait,
    //      test_mma.cu pattern); warps 4-31 fall through to the join BAR ---
    if (wid < 4) {
        MBAR_WAITP(base + 8, 0);
        asm volatile("tcgen05.fence::after_thread_sync;" ::: "memory");

        // Both LDTM x16 issued, then ONE wait.
        uint32_t d0[16], d1[16];
        LDTM_X16(d0, tmem);
        LDTM_X16(d1, tmem + 16);
        asm volatile("tcgen05.wait::ld.sync.aligned;" ::: "memory");

        float* pp = &gPart[kz][(size_t)(m0 + wid * 32 + lid) * ND + n0];
#pragma unroll
        for (int g = 0; g < 4; g++) {
            float4 r;
            r.x = __uint_as_float(d0[4 * g + 0]);
            r.y = __uint_as_float(d0[4 * g + 1]);
            r.z = __uint_as_float(d0[4 * g + 2]);
            r.w = __uint_as_float(d0[4 * g + 3]);
            *(float4*)(pp + 4 * g) = r;
            float4 r2;
            r2.x = __uint_as_float(d1[4 * g + 0]);
            r2.y = __uint_as_float(d1[4 * g + 1]);
            r2.z = __uint_as_float(d1[4 * g + 2]);
            r2.w = __uint_as_float(d1[4 * g + 3]);
            *(float4*)(pp + 16 + 4 * g) = r2;
        }
    }

    // ---- join: warp1 deallocs TMEM in PARALLEL with tid0's atomic --------
    __syncthreads();                      // STGs + all TMEM reads complete
    if (wid == 1) {
        asm volatile("tcgen05.relinquish_alloc_permit.cta_group::1.sync.aligned;");
        asm volatile("tcgen05.dealloc.cta_group::1.sync.aligned.b32 %0, %1;"
                     :: "r"(tmem), "r"(32u));
    }
    if (tid == 0) {
        asm volatile("fence.acq_rel.gpu;" ::: "memory");
        const int old = atomicAdd(&gCnt[tile], 1);
        asm volatile("fence.acq_rel.gpu;" ::: "memory");
        *(int*)(dbase + 64) = (old == 1);
    }
    __syncthreads();

    if (*(int*)(dbase + 64)) {
        // Winner: one float4 of output per thread (1024 x 4 = 4096 = tile).
        const int row = tid >> 3, q = tid & 7;
        const size_t idx = (size_t)(m0 + row) * ND + n0 + 4 * q;
        float4 p0 = *(const float4*)&gPart[0][idx];
        float4 p1 = *(const float4*)&gPart[1][idx];
        float4 bb = *(const float4*)(dbase + 128 + 16 * q);
        float4 r;
        r.x = p0.x + p1.x + bb.x;
        r.y = p0.y + p1.y + bb.y;
        r.z = p0.z + p1.z + bb.z;
        r.w = p0.w + p1.w + bb.w;
        *(float4*)(Y + idx) = r;
        if (tid == 0) gCnt[tile] = 0;     // reset for next graph replay
    }
    // no trailing sync: each warp exits when its own tail is done
#else
    // ---- generic-target fallback (compiles everywhere; never runs) -------
    __shared__ int sflag;
    const int r = tid >> 3;               // 0..127
    const int g = tid & 7;                // 4 n cols each
    float acc[4];
#pragma unroll
    for (int j = 0; j < 4; j++) acc[j] = 0.f;
    for (int k = kz * KH; k < kz * KH + KH; k++) {
        const float a = X[(size_t)(m0 + r) * KD + k];
        const float* wr = W + (size_t)k * ND + n0 + 4 * g;
#pragma unroll
        for (int j = 0; j < 4; j++) acc[j] += a * wr[j];
    }
    {
        float* pp = &gPart[kz][(size_t)(m0 + r) * ND + n0 + 4 * g];
#pragma unroll
        for (int j = 0; j < 4; j++) pp[j] = acc[j];
    }
    __threadfence();
    __syncthreads();
    if (tid == 0) sflag = (atomicAdd(&gCnt[tile], 1) == 1);
    __syncthreads();
    if (sflag) {
        __threadfence();
        const size_t idx = (size_t)(m0 + r) * ND + n0 + 4 * g;
        float4 p0 = *(const float4*)&gPart[0][idx];
        float4 p1 = *(const float4*)&gPart[1][idx];
        const float* bb = Bias + n0 + 4 * g;
        float4 rr;
        rr.x = p0.x + p1.x + bb[0];
        rr.y = p0.y + p1.y + bb[1];
        rr.z = p0.z + p1.z + bb[2];
        rr.w = p0.w + p1.w + bb[3];
        *(float4*)(Y + idx) = rr;
        if (tid == 0) gCnt[tile] = 0;
    }
#endif
}

extern "C" void kernel_launch(void* const* d_in, const int* in_sizes, int n_in,
                              void* d_out, int out_size) {
    const float* x = (const float*)d_in[0];  // [512, 512]
    const float* w = (const float*)d_in[1];  // [512, 512]
    const float* b = (const float*)d_in[2];  // [512]
    float* y = (float*)d_out;                // [512, 512]

    static bool attr_done = false;
    if (!attr_done) {
        cudaFuncSetAttribute(fused_kernel,
                             cudaFuncAttributeMaxDynamicSharedMemorySize,
                             SMEM_DYN);
        attr_done = true;
    }

    dim3 grid(ND / 32, MD / 128, 2);  // (16, 4, 2) = 128 CTAs, one wave
    fused_kernel<<<grid, NT, SMEM_DYN>>>(x, w, b, y);
}